// round 1
// baseline (speedup 1.0000x reference)
#include <cuda_runtime.h>
#include <math.h>

#define N_NODES 30000
#define N_EDGES 480000
#define B_PAIRS 4096
#define CDIV(a,b) (((a)+(b)-1)/(b))

// ---------------- scratch (static device memory; no allocations) ----------------
__device__ float g_x881[N_NODES * 881];     // after bb_fc2 (+softthr)
__device__ float g_h[N_NODES * 256];        // current node features
__device__ float g_t[N_NODES * 256];        // h @ W temp
__device__ float g_dinv[N_NODES];
__device__ int   g_cnt[N_NODES];
__device__ int   g_fill[N_NODES];
__device__ int   g_rowptr[N_NODES + 1];
__device__ int   g_col[N_EDGES];
__device__ float g_w[N_EDGES];
__device__ float g_xc[B_PAIRS * 256];
__device__ float g_p1[B_PAIRS * 1024];
__device__ float g_p3[B_PAIRS * 64];
__device__ int   g_is64;

// ---------------- index dtype detection (int64 vs int32) ----------------
// If indices are int64 (values < 2^31, nonnegative), every odd 32-bit word is 0.
__global__ void k_detect(const unsigned int* p) {
    __shared__ int any;
    if (threadIdx.x == 0) any = 0;
    __syncthreads();
    for (int i = threadIdx.x; i < 2048; i += blockDim.x)
        if (p[2 * i + 1] != 0u) any = 1;
    __syncthreads();
    if (threadIdx.x == 0) g_is64 = (any == 0);
}

__device__ __forceinline__ int ld_idx(const void* p, long long i) {
    if (g_is64) return (int)((const long long*)p)[i];
    return ((const int*)p)[i];
}

// ---------------- graph preprocessing ----------------
__global__ void k_zero() {
    int i = blockIdx.x * blockDim.x + threadIdx.x;
    if (i < N_NODES) { g_cnt[i] = 0; g_fill[i] = 0; }
}

__global__ void k_count(const void* edges) {
    int e = blockIdx.x * blockDim.x + threadIdx.x;
    if (e >= N_EDGES) return;
    int d = ld_idx(edges, (long long)N_EDGES + e);   // link_edge[1][e]
    atomicAdd(&g_cnt[d], 1);
}

__global__ void k_dinv() {
    int i = blockIdx.x * blockDim.x + threadIdx.x;
    if (i < N_NODES) g_dinv[i] = rsqrtf((float)(g_cnt[i] + 1));  // +1 self loop
}

// single-block exclusive scan of g_cnt -> g_rowptr
__global__ void k_scan() {
    __shared__ int s[1024];
    __shared__ int carry;
    int t = threadIdx.x;
    if (t == 0) { carry = 0; g_rowptr[0] = 0; }
    __syncthreads();
    for (int base = 0; base < N_NODES; base += 1024) {
        int i = base + t;
        int v = (i < N_NODES) ? g_cnt[i] : 0;
        s[t] = v;
        __syncthreads();
        for (int off = 1; off < 1024; off <<= 1) {
            int add = (t >= off) ? s[t - off] : 0;
            __syncthreads();
            s[t] += add;
            __syncthreads();
        }
        if (i < N_NODES) g_rowptr[i + 1] = carry + s[t];
        __syncthreads();
        if (t == 0) carry += s[1023];
        __syncthreads();
    }
}

__global__ void k_fill(const void* edges) {
    int e = blockIdx.x * blockDim.x + threadIdx.x;
    if (e >= N_EDGES) return;
    int s = ld_idx(edges, e);
    int d = ld_idx(edges, (long long)N_EDGES + e);
    int pos = g_rowptr[d] + atomicAdd(&g_fill[d], 1);
    g_col[pos] = s;
    g_w[pos] = g_dinv[s] * g_dinv[d];
}

// ---------------- tiled fp32 GEMM: C = epi(A[M,K] @ B[K,N] + bias) ----------------
// EPI 0: none  1: relu(z+b)  2: max(z+b-thr, 0)   (soft-threshold after relu, thr>=0)
template <int EPI>
__global__ __launch_bounds__(256) void k_gemm(
    const float* __restrict__ A, const float* __restrict__ B,
    const float* __restrict__ bias, float* __restrict__ C,
    int M, int Kd, int Nd, const float* __restrict__ thrp)
{
    const int BM = 64, BN = 64, BK = 16;
    __shared__ float As[BK][BM];
    __shared__ float Bs[BK][BN];

    int tid = threadIdx.x;
    int tx = tid & 15;        // 0..15 -> 4 output cols each
    int ty = tid >> 4;        // 0..15 -> 4 output rows each
    int m0 = blockIdx.y * BM;
    int n0 = blockIdx.x * BN;

    int lkA = tid & 15;       // k within tile
    int lmA = tid >> 4;       // row base
    int lnB = tid & 63;
    int lkB = tid >> 6;

    float acc[4][4];
#pragma unroll
    for (int i = 0; i < 4; i++)
#pragma unroll
        for (int j = 0; j < 4; j++) acc[i][j] = 0.f;

    for (int k0 = 0; k0 < Kd; k0 += BK) {
#pragma unroll
        for (int i = 0; i < 4; i++) {
            int m = m0 + lmA + 16 * i;
            int k = k0 + lkA;
            As[lkA][lmA + 16 * i] = (m < M && k < Kd) ? A[(size_t)m * Kd + k] : 0.f;
        }
#pragma unroll
        for (int i = 0; i < 4; i++) {
            int k = k0 + lkB + 4 * i;
            int n = n0 + lnB;
            Bs[lkB + 4 * i][lnB] = (k < Kd && n < Nd) ? B[(size_t)k * Nd + n] : 0.f;
        }
        __syncthreads();
#pragma unroll
        for (int kk = 0; kk < BK; kk++) {
            float4 a = *(const float4*)&As[kk][ty * 4];
            float4 b = *(const float4*)&Bs[kk][tx * 4];
            acc[0][0] += a.x * b.x; acc[0][1] += a.x * b.y; acc[0][2] += a.x * b.z; acc[0][3] += a.x * b.w;
            acc[1][0] += a.y * b.x; acc[1][1] += a.y * b.y; acc[1][2] += a.y * b.z; acc[1][3] += a.y * b.w;
            acc[2][0] += a.z * b.x; acc[2][1] += a.z * b.y; acc[2][2] += a.z * b.z; acc[2][3] += a.z * b.w;
            acc[3][0] += a.w * b.x; acc[3][1] += a.w * b.y; acc[3][2] += a.w * b.z; acc[3][3] += a.w * b.w;
        }
        __syncthreads();
    }

    float thr = 0.f;
    if (EPI == 2) thr = *thrp;
#pragma unroll
    for (int i = 0; i < 4; i++) {
        int m = m0 + ty * 4 + i;
        if (m >= M) continue;
#pragma unroll
        for (int j = 0; j < 4; j++) {
            int n = n0 + tx * 4 + j;
            if (n >= Nd) continue;
            float z = acc[i][j];
            if (bias) z += bias[n];
            if (EPI == 1) z = fmaxf(z, 0.f);
            if (EPI == 2) z = fmaxf(z - thr, 0.f);
            C[(size_t)m * Nd + n] = z;
        }
    }
}

// ---------------- GCN aggregation: h[i] = elu(sum_{j->i} w*t[j] + dinv_i^2*t[i] + b) --------
template <int F>
__global__ void k_agg(const float* __restrict__ t, const float* __restrict__ bias,
                      float* __restrict__ h)
{
    int node = blockIdx.x;
    int f = threadIdx.x;
    float di = g_dinv[node];
    float acc = di * di * t[(size_t)node * F + f];
    int beg = g_rowptr[node], end = g_rowptr[node + 1];
    __shared__ int scol[128];
    __shared__ float sw[128];
    for (int base = beg; base < end; base += 128) {
        int nchunk = min(128, end - base);
        __syncthreads();
        if (f < nchunk) { scol[f] = g_col[base + f]; sw[f] = g_w[base + f]; }
        __syncthreads();
        for (int j = 0; j < nchunk; j++)
            acc += sw[j] * t[(size_t)scol[j] * F + f];
    }
    float z = acc + bias[f];
    h[(size_t)node * F + f] = (z > 0.f) ? z : expm1f(z);
}

// ---------------- pair gather + L2 normalize ----------------
__global__ void k_pairs(const float* __restrict__ h, const void* i1, const void* i2) {
    int b = blockIdx.x;
    int k = threadIdx.x;  // 128
    int a1 = ld_idx(i1, b), a2 = ld_idx(i2, b);
    float v1 = h[(size_t)a1 * 128 + k];
    float v2 = h[(size_t)a2 * 128 + k];
    float s = v1 * v1 + v2 * v2;
    __shared__ float red[4];
#pragma unroll
    for (int o = 16; o; o >>= 1) s += __shfl_down_sync(0xffffffffu, s, o);
    if ((k & 31) == 0) red[k >> 5] = s;
    __syncthreads();
    float tot = red[0] + red[1] + red[2] + red[3];
    float nrm = fmaxf(sqrtf(tot), 1e-12f);
    float inv = 1.f / nrm;
    g_xc[(size_t)b * 256 + k] = v1 * inv;
    g_xc[(size_t)b * 256 + 128 + k] = v2 * inv;
}

// ---------------- final 64->2 linear ----------------
__global__ void k_out(const float* __restrict__ W, const float* __restrict__ bias,
                      float* __restrict__ out) {
    int b = blockIdx.x;
    int lane = threadIdx.x;  // 32
    float a0 = 0.f, a1 = 0.f;
    for (int k = lane; k < 64; k += 32) {
        float v = g_p3[(size_t)b * 64 + k];
        a0 += v * W[k * 2 + 0];
        a1 += v * W[k * 2 + 1];
    }
#pragma unroll
    for (int o = 16; o; o >>= 1) {
        a0 += __shfl_down_sync(0xffffffffu, a0, o);
        a1 += __shfl_down_sync(0xffffffffu, a1, o);
    }
    if (lane == 0) {
        out[b * 2 + 0] = a0 + bias[0];
        out[b * 2 + 1] = a1 + bias[1];
    }
}

// ---------------- launch ----------------
extern "C" void kernel_launch(void* const* d_in, const int* in_sizes, int n_in,
                              void* d_out, int out_size)
{
    const float* cid   = (const float*)d_in[0];
    const void*  edges = d_in[1];
    const void*  i1    = d_in[2];
    const void*  i2    = d_in[3];
    const float* thr   = (const float*)d_in[4];
    const float* bbW2  = (const float*)d_in[5];
    const float* bbb2  = (const float*)d_in[6];
    const float* bbW3  = (const float*)d_in[7];
    const float* bbb3  = (const float*)d_in[8];
    const float* gW[5] = {(const float*)d_in[9],  (const float*)d_in[11],
                          (const float*)d_in[13], (const float*)d_in[15],
                          (const float*)d_in[17]};
    const float* gb[5] = {(const float*)d_in[10], (const float*)d_in[12],
                          (const float*)d_in[14], (const float*)d_in[16],
                          (const float*)d_in[18]};
    const float* fc1W = (const float*)d_in[19];
    const float* fc1b = (const float*)d_in[20];
    const float* fc2W = (const float*)d_in[21];
    const float* fc2b = (const float*)d_in[22];
    const float* fc3W = (const float*)d_in[23];
    const float* fc3b = (const float*)d_in[24];
    const float* oW   = (const float*)d_in[25];
    const float* ob   = (const float*)d_in[26];
    float* out = (float*)d_out;

    float *x881, *h, *t, *xc, *p1, *p3;
    cudaGetSymbolAddress((void**)&x881, g_x881);
    cudaGetSymbolAddress((void**)&h,    g_h);
    cudaGetSymbolAddress((void**)&t,    g_t);
    cudaGetSymbolAddress((void**)&xc,   g_xc);
    cudaGetSymbolAddress((void**)&p1,   g_p1);
    cudaGetSymbolAddress((void**)&p3,   g_p3);

    // graph preprocessing
    k_detect<<<1, 256>>>((const unsigned int*)edges);
    k_zero<<<CDIV(N_NODES, 256), 256>>>();
    k_count<<<CDIV(N_EDGES, 256), 256>>>(edges);
    k_dinv<<<CDIV(N_NODES, 256), 256>>>();
    k_scan<<<1, 1024>>>();
    k_fill<<<CDIV(N_EDGES, 256), 256>>>(edges);

    // BasicBlock: relu(cid@W2+b2) soft-thresholded; relu(x@W3+b3)
    k_gemm<2><<<dim3(CDIV(881, 64), CDIV(N_NODES, 64)), 256>>>(
        cid, bbW2, bbb2, x881, N_NODES, 881, 881, thr);
    k_gemm<1><<<dim3(CDIV(256, 64), CDIV(N_NODES, 64)), 256>>>(
        x881, bbW3, bbb3, h, N_NODES, 881, 256, nullptr);

    // 5 GCN layers
    const int fin[5]  = {256, 256, 256, 256, 128};
    const int fout[5] = {256, 256, 256, 128, 128};
    for (int l = 0; l < 5; l++) {
        k_gemm<0><<<dim3(CDIV(fout[l], 64), CDIV(N_NODES, 64)), 256>>>(
            h, gW[l], nullptr, t, N_NODES, fin[l], fout[l], nullptr);
        if (fout[l] == 256)
            k_agg<256><<<N_NODES, 256>>>(t, gb[l], h);
        else
            k_agg<128><<<N_NODES, 128>>>(t, gb[l], h);
    }

    // pair readout
    k_pairs<<<B_PAIRS, 128>>>(h, i1, i2);
    k_gemm<1><<<dim3(CDIV(1024, 64), CDIV(B_PAIRS, 64)), 256>>>(
        xc, fc1W, fc1b, p1, B_PAIRS, 256, 1024, nullptr);
    k_gemm<1><<<dim3(CDIV(256, 64), CDIV(B_PAIRS, 64)), 256>>>(
        p1, fc2W, fc2b, xc, B_PAIRS, 1024, 256, nullptr);
    k_gemm<1><<<dim3(CDIV(64, 64), CDIV(B_PAIRS, 64)), 256>>>(
        xc, fc3W, fc3b, p3, B_PAIRS, 256, 64, nullptr);
    k_out<<<B_PAIRS, 32>>>(oW, ob, out);
}

// round 3
// speedup vs baseline: 1.1897x; 1.1897x over previous
#include <cuda_runtime.h>
#include <math.h>

#define N_NODES 30000
#define N_EDGES 480000
#define B_PAIRS 4096
#define CDIV(a,b) (((a)+(b)-1)/(b))

// ---------------- scratch (static device memory; no allocations) ----------------
__device__ float g_x881[N_NODES * 881];
__device__ float g_h[N_NODES * 256];
__device__ float g_t[N_NODES * 256];
__device__ float g_dinv[N_NODES];
__device__ int   g_cnt[N_NODES];
__device__ int   g_fill[N_NODES];
__device__ int   g_rowptr[N_NODES + 1];
__device__ int   g_col[N_EDGES];
__device__ float g_w[N_EDGES];
__device__ float g_xc[B_PAIRS * 256];
__device__ float g_p1[B_PAIRS * 1024];
__device__ float g_p3[B_PAIRS * 64];
__device__ int   g_is64;

// ---------------- fused init: zero counters + detect index dtype ----------------
__global__ void k_init(const unsigned int* p) {
    int i = blockIdx.x * blockDim.x + threadIdx.x;
    if (i < N_NODES) { g_cnt[i] = 0; g_fill[i] = 0; }
    if (blockIdx.x == 0) {
        __shared__ int any;
        if (threadIdx.x == 0) any = 0;
        __syncthreads();
        int loc = 0;
        for (int j = threadIdx.x; j < 2048; j += blockDim.x)
            if (p[2 * j + 1] != 0u) loc = 1;
        if (loc) any = 1;
        __syncthreads();
        if (threadIdx.x == 0) g_is64 = (any == 0);
    }
}

__device__ __forceinline__ int ld_idx(const void* p, long long i) {
    if (g_is64) return (int)((const long long*)p)[i];
    return ((const int*)p)[i];
}

// ---------------- graph preprocessing ----------------
__global__ void k_count(const void* edges) {
    int e = blockIdx.x * blockDim.x + threadIdx.x;
    if (e >= N_EDGES) return;
    int d = ld_idx(edges, (long long)N_EDGES + e);
    atomicAdd(&g_cnt[d], 1);
}

__global__ void k_dinv() {
    int i = blockIdx.x * blockDim.x + threadIdx.x;
    if (i < N_NODES) g_dinv[i] = rsqrtf((float)(g_cnt[i] + 1));
}

__global__ void k_scan() {
    __shared__ int s[1024];
    __shared__ int carry;
    int t = threadIdx.x;
    if (t == 0) { carry = 0; g_rowptr[0] = 0; }
    __syncthreads();
    for (int base = 0; base < N_NODES; base += 1024) {
        int i = base + t;
        int v = (i < N_NODES) ? g_cnt[i] : 0;
        s[t] = v;
        __syncthreads();
        for (int off = 1; off < 1024; off <<= 1) {
            int add = (t >= off) ? s[t - off] : 0;
            __syncthreads();
            s[t] += add;
            __syncthreads();
        }
        if (i < N_NODES) g_rowptr[i + 1] = carry + s[t];
        __syncthreads();
        if (t == 0) carry += s[1023];
        __syncthreads();
    }
}

__global__ void k_fill(const void* edges) {
    int e = blockIdx.x * blockDim.x + threadIdx.x;
    if (e >= N_EDGES) return;
    int s = ld_idx(edges, e);
    int d = ld_idx(edges, (long long)N_EDGES + e);
    int pos = g_rowptr[d] + atomicAdd(&g_fill[d], 1);
    g_col[pos] = s;
    g_w[pos] = g_dinv[s] * g_dinv[d];
}

// ---------------- 128x128x8 double-buffered fp32 GEMM, 8x8 micro-tile ----------------
// C = epi(A[M,K] @ B[K,N] + bias)
// EPI 0: none  1: relu  2: relu then soft-threshold (max(z-thr,0), thr>=0)
template <int EPI>
__global__ __launch_bounds__(256, 2) void k_gemm128(
    const float* __restrict__ A, const float* __restrict__ B,
    const float* __restrict__ bias, float* __restrict__ C,
    int M, int K, int N, const float* __restrict__ thrp)
{
    const int BM = 128, BN = 128, BK = 8;
    __shared__ float As[2][BK][BM];
    __shared__ float Bs[2][BK][BN];

    int tid = threadIdx.x;
    int tx = tid & 15;         // output col group (8 cols each)
    int ty = tid >> 4;         // output row group (8 rows each)
    int m0 = blockIdx.y * BM;
    int n0 = blockIdx.x * BN;

    // A loader: thread -> row (tid>>1), 4 consecutive k at (tid&1)*4
    int ar = tid >> 1;
    int ac = (tid & 1) * 4;
    // B loader: thread -> k-row (tid>>5), 4 consecutive n at (tid&31)*4
    int br = tid >> 5;
    int bc = (tid & 31) * 4;

    const float* Arow = A + (size_t)(m0 + ar) * K;
    bool aRowOk = (m0 + ar) < M;

    float acc[8][8];
#pragma unroll
    for (int i = 0; i < 8; i++)
#pragma unroll
        for (int j = 0; j < 8; j++) acc[i][j] = 0.f;

    int nch = CDIV(K, BK);
    float rA[4], rB[4];

    // prologue: load chunk 0 into buffer 0
    {
#pragma unroll
        for (int j = 0; j < 4; j++) {
            int k = ac + j;
            rA[j] = (aRowOk && k < K) ? Arow[k] : 0.f;
        }
#pragma unroll
        for (int j = 0; j < 4; j++) {
            int k = br;
            int n = n0 + bc + j;
            rB[j] = (k < K && n < N) ? B[(size_t)k * N + n] : 0.f;
        }
#pragma unroll
        for (int j = 0; j < 4; j++) As[0][ac + j][ar] = rA[j];
        *(float4*)&Bs[0][br][bc] = make_float4(rB[0], rB[1], rB[2], rB[3]);
    }
    __syncthreads();

    int cur = 0;
    for (int ch = 0; ch < nch; ch++) {
        bool more = (ch + 1) < nch;
        if (more) {
            int k0 = (ch + 1) * BK;
#pragma unroll
            for (int j = 0; j < 4; j++) {
                int k = k0 + ac + j;
                rA[j] = (aRowOk && k < K) ? Arow[k] : 0.f;
            }
#pragma unroll
            for (int j = 0; j < 4; j++) {
                int k = k0 + br;
                int n = n0 + bc + j;
                rB[j] = (k < K && n < N) ? B[(size_t)k * N + n] : 0.f;
            }
        }
#pragma unroll
        for (int kk = 0; kk < BK; kk++) {
            float4 a0 = *(const float4*)&As[cur][kk][ty * 8];
            float4 a1 = *(const float4*)&As[cur][kk][ty * 8 + 4];
            float4 b0 = *(const float4*)&Bs[cur][kk][tx * 8];
            float4 b1 = *(const float4*)&Bs[cur][kk][tx * 8 + 4];
            float av[8] = {a0.x, a0.y, a0.z, a0.w, a1.x, a1.y, a1.z, a1.w};
            float bv[8] = {b0.x, b0.y, b0.z, b0.w, b1.x, b1.y, b1.z, b1.w};
#pragma unroll
            for (int i = 0; i < 8; i++)
#pragma unroll
                for (int j = 0; j < 8; j++)
                    acc[i][j] += av[i] * bv[j];
        }
        if (more) {
            int nxt = cur ^ 1;
#pragma unroll
            for (int j = 0; j < 4; j++) As[nxt][ac + j][ar] = rA[j];
            *(float4*)&Bs[nxt][br][bc] = make_float4(rB[0], rB[1], rB[2], rB[3]);
        }
        __syncthreads();
        cur ^= 1;
    }

    float thr = 0.f;
    if (EPI == 2) thr = *thrp;
    float bj[8];
#pragma unroll
    for (int j = 0; j < 8; j++) {
        int n = n0 + tx * 8 + j;
        bj[j] = (bias && n < N) ? bias[n] : 0.f;
    }
#pragma unroll
    for (int i = 0; i < 8; i++) {
        int m = m0 + ty * 8 + i;
        if (m >= M) continue;
#pragma unroll
        for (int j = 0; j < 8; j++) {
            int n = n0 + tx * 8 + j;
            if (n >= N) continue;
            float z = acc[i][j] + bj[j];
            if (EPI == 1) z = fmaxf(z, 0.f);
            if (EPI == 2) z = fmaxf(z - thr, 0.f);
            C[(size_t)m * N + n] = z;
        }
    }
}

// ---------------- GCN aggregation: h[i] = elu(sum_{j->i} w*t[j] + dinv_i^2*t[i] + b) ----
template <int F>
__global__ void k_agg(const float* __restrict__ t, const float* __restrict__ bias,
                      float* __restrict__ h)
{
    int node = blockIdx.x;
    int f = threadIdx.x;
    float di = g_dinv[node];
    float acc = di * di * t[(size_t)node * F + f];
    int beg = g_rowptr[node], end = g_rowptr[node + 1];
    __shared__ int scol[128];
    __shared__ float sw[128];
    for (int base = beg; base < end; base += 128) {
        int nchunk = min(128, end - base);
        __syncthreads();
        if (f < nchunk) { scol[f] = g_col[base + f]; sw[f] = g_w[base + f]; }
        __syncthreads();
        for (int j = 0; j < nchunk; j++)
            acc += sw[j] * t[(size_t)scol[j] * F + f];
    }
    float z = acc + bias[f];
    h[(size_t)node * F + f] = (z > 0.f) ? z : expm1f(z);
}

// ---------------- pair gather + L2 normalize ----------------
__global__ void k_pairs(const float* __restrict__ h, const void* i1, const void* i2) {
    int b = blockIdx.x;
    int k = threadIdx.x;  // 128
    int a1 = ld_idx(i1, b), a2 = ld_idx(i2, b);
    float v1 = h[(size_t)a1 * 128 + k];
    float v2 = h[(size_t)a2 * 128 + k];
    float s = v1 * v1 + v2 * v2;
    __shared__ float red[4];
#pragma unroll
    for (int o = 16; o; o >>= 1) s += __shfl_down_sync(0xffffffffu, s, o);
    if ((k & 31) == 0) red[k >> 5] = s;
    __syncthreads();
    float tot = red[0] + red[1] + red[2] + red[3];
    float nrm = fmaxf(sqrtf(tot), 1e-12f);
    float inv = 1.f / nrm;
    g_xc[(size_t)b * 256 + k] = v1 * inv;
    g_xc[(size_t)b * 256 + 128 + k] = v2 * inv;
}

// ---------------- final 64->2 linear ----------------
__global__ void k_out(const float* __restrict__ W, const float* __restrict__ bias,
                      float* __restrict__ out) {
    int b = blockIdx.x;
    int lane = threadIdx.x;  // 32
    float a0 = 0.f, a1 = 0.f;
    for (int k = lane; k < 64; k += 32) {
        float v = g_p3[(size_t)b * 64 + k];
        a0 += v * W[k * 2 + 0];
        a1 += v * W[k * 2 + 1];
    }
#pragma unroll
    for (int o = 16; o; o >>= 1) {
        a0 += __shfl_down_sync(0xffffffffu, a0, o);
        a1 += __shfl_down_sync(0xffffffffu, a1, o);
    }
    if (lane == 0) {
        out[b * 2 + 0] = a0 + bias[0];
        out[b * 2 + 1] = a1 + bias[1];
    }
}

// ---------------- launch ----------------
extern "C" void kernel_launch(void* const* d_in, const int* in_sizes, int n_in,
                              void* d_out, int out_size)
{
    const float* cid   = (const float*)d_in[0];
    const void*  edges = d_in[1];
    const void*  i1    = d_in[2];
    const void*  i2    = d_in[3];
    const float* thr   = (const float*)d_in[4];
    const float* bbW2  = (const float*)d_in[5];
    const float* bbb2  = (const float*)d_in[6];
    const float* bbW3  = (const float*)d_in[7];
    const float* bbb3  = (const float*)d_in[8];
    const float* gW[5] = {(const float*)d_in[9],  (const float*)d_in[11],
                          (const float*)d_in[13], (const float*)d_in[15],
                          (const float*)d_in[17]};
    const float* gb[5] = {(const float*)d_in[10], (const float*)d_in[12],
                          (const float*)d_in[14], (const float*)d_in[16],
                          (const float*)d_in[18]};
    const float* fc1W = (const float*)d_in[19];
    const float* fc1b = (const float*)d_in[20];
    const float* fc2W = (const float*)d_in[21];
    const float* fc2b = (const float*)d_in[22];
    const float* fc3W = (const float*)d_in[23];
    const float* fc3b = (const float*)d_in[24];
    const float* oW   = (const float*)d_in[25];
    const float* ob   = (const float*)d_in[26];
    float* out = (float*)d_out;

    float *x881, *h, *t, *xc, *p1, *p3;
    cudaGetSymbolAddress((void**)&x881, g_x881);
    cudaGetSymbolAddress((void**)&h,    g_h);
    cudaGetSymbolAddress((void**)&t,    g_t);
    cudaGetSymbolAddress((void**)&xc,   g_xc);
    cudaGetSymbolAddress((void**)&p1,   g_p1);
    cudaGetSymbolAddress((void**)&p3,   g_p3);

    // graph preprocessing (5 launches; launch #6 = big GEMM for ncu -s 5 -c 1)
    k_init<<<CDIV(N_NODES, 256), 256>>>((const unsigned int*)edges);
    k_count<<<CDIV(N_EDGES, 256), 256>>>(edges);
    k_dinv<<<CDIV(N_NODES, 256), 256>>>();
    k_scan<<<1, 1024>>>();
    k_fill<<<CDIV(N_EDGES, 256), 256>>>(edges);

    // BasicBlock
    k_gemm128<2><<<dim3(CDIV(881, 128), CDIV(N_NODES, 128)), 256>>>(
        cid, bbW2, bbb2, x881, N_NODES, 881, 881, thr);
    k_gemm128<1><<<dim3(CDIV(256, 128), CDIV(N_NODES, 128)), 256>>>(
        x881, bbW3, bbb3, h, N_NODES, 881, 256, nullptr);

    // 5 GCN layers
    const int fin[5]  = {256, 256, 256, 256, 128};
    const int fout[5] = {256, 256, 256, 128, 128};
    for (int l = 0; l < 5; l++) {
        k_gemm128<0><<<dim3(CDIV(fout[l], 128), CDIV(N_NODES, 128)), 256>>>(
            h, gW[l], nullptr, t, N_NODES, fin[l], fout[l], nullptr);
        if (fout[l] == 256)
            k_agg<256><<<N_NODES, 256>>>(t, gb[l], h);
        else
            k_agg<128><<<N_NODES, 128>>>(t, gb[l], h);
    }

    // pair readout
    k_pairs<<<B_PAIRS, 128>>>(h, i1, i2);
    k_gemm128<1><<<dim3(CDIV(1024, 128), CDIV(B_PAIRS, 128)), 256>>>(
        xc, fc1W, fc1b, p1, B_PAIRS, 256, 1024, nullptr);
    k_gemm128<1><<<dim3(CDIV(256, 128), CDIV(B_PAIRS, 128)), 256>>>(
        p1, fc2W, fc2b, xc, B_PAIRS, 1024, 256, nullptr);
    k_gemm128<1><<<dim3(CDIV(64, 128), CDIV(B_PAIRS, 128)), 256>>>(
        xc, fc3W, fc3b, p3, B_PAIRS, 256, 64, nullptr);
    k_out<<<B_PAIRS, 32>>>(oW, ob, out);
}

// round 7
// speedup vs baseline: 1.5369x; 1.2919x over previous
#include <cuda_runtime.h>
#include <cuda_bf16.h>
#include <math.h>
#include <stdint.h>

#define N_NODES 30000
#define N_EDGES 480000
#define B_PAIRS 4096
#define CDIV(a,b) (((a)+(b)-1)/(b))

// ---------------- scratch (static device memory; no allocations) ----------------
__device__ float g_x881[N_NODES * 881];
__device__ float g_h[N_NODES * 256];
__device__ float g_t[N_NODES * 256];
__device__ float g_dinv[N_NODES];
__device__ int   g_cnt[N_NODES];
__device__ int   g_fill[N_NODES];
__device__ int   g_rowptr[N_NODES + 1];
__device__ int   g_col[N_EDGES];
__device__ float g_w[N_EDGES];
__device__ float g_xc[B_PAIRS * 256];
__device__ float g_p1[B_PAIRS * 1024];
__device__ float g_p3[B_PAIRS * 64];
__device__ int   g_is64;

// ---------------- fused init: zero counters + detect index dtype ----------------
__global__ void k_init(const unsigned int* p) {
    int i = blockIdx.x * blockDim.x + threadIdx.x;
    if (i < N_NODES) { g_cnt[i] = 0; g_fill[i] = 0; }
    if (blockIdx.x == 0) {
        __shared__ int any;
        if (threadIdx.x == 0) any = 0;
        __syncthreads();
        int loc = 0;
        for (int j = threadIdx.x; j < 2048; j += blockDim.x)
            if (p[2 * j + 1] != 0u) loc = 1;
        if (loc) any = 1;
        __syncthreads();
        if (threadIdx.x == 0) g_is64 = (any == 0);
    }
}

__device__ __forceinline__ int ld_idx(const void* p, long long i) {
    if (g_is64) return (int)((const long long*)p)[i];
    return ((const int*)p)[i];
}

// ---------------- graph preprocessing ----------------
__global__ void k_count(const void* edges) {
    int e = blockIdx.x * blockDim.x + threadIdx.x;
    if (e >= N_EDGES) return;
    int d = ld_idx(edges, (long long)N_EDGES + e);
    atomicAdd(&g_cnt[d], 1);
}

__global__ void k_dinv() {
    int i = blockIdx.x * blockDim.x + threadIdx.x;
    if (i < N_NODES) g_dinv[i] = rsqrtf((float)(g_cnt[i] + 1));
}

__global__ void k_scan() {
    __shared__ int s[1024];
    __shared__ int carry;
    int t = threadIdx.x;
    if (t == 0) { carry = 0; g_rowptr[0] = 0; }
    __syncthreads();
    for (int base = 0; base < N_NODES; base += 1024) {
        int i = base + t;
        int v = (i < N_NODES) ? g_cnt[i] : 0;
        s[t] = v;
        __syncthreads();
        for (int off = 1; off < 1024; off <<= 1) {
            int add = (t >= off) ? s[t - off] : 0;
            __syncthreads();
            s[t] += add;
            __syncthreads();
        }
        if (i < N_NODES) g_rowptr[i + 1] = carry + s[t];
        __syncthreads();
        if (t == 0) carry += s[1023];
        __syncthreads();
    }
}

__global__ void k_fill(const void* edges) {
    int e = blockIdx.x * blockDim.x + threadIdx.x;
    if (e >= N_EDGES) return;
    int s = ld_idx(edges, e);
    int d = ld_idx(edges, (long long)N_EDGES + e);
    int pos = g_rowptr[d] + atomicAdd(&g_fill[d], 1);
    g_col[pos] = s;
    g_w[pos] = g_dinv[s] * g_dinv[d];
}

// =====================================================================
// bf16-split tensor GEMM:  C = epi(A[M,K] @ B[K,N] + bias)
// fp32 inputs split on the fly: a = ahi + alo (bf16 each);
// C ≈ Ahi Bhi + Ahi Blo + Alo Bhi  (3 HMMA passes, fp32 accum)
// Block 128x128, 8 warps (2m x 4n), warp tile 64x32, BK=16, double buffered.
// EPI 0: none  1: relu  2: relu+soft-threshold (max(z-thr,0), thr>=0)
// =====================================================================
#define MMA_BF16(d, a, b) \
    asm volatile("mma.sync.aligned.m16n8k16.row.col.f32.bf16.bf16.f32 " \
                 "{%0,%1,%2,%3},{%4,%5,%6,%7},{%8,%9},{%0,%1,%2,%3};" \
                 : "+f"(d[0]), "+f"(d[1]), "+f"(d[2]), "+f"(d[3]) \
                 : "r"(a[0]), "r"(a[1]), "r"(a[2]), "r"(a[3]), "r"(b[0]), "r"(b[1]))

template <int EPI>
__global__ __launch_bounds__(256) void k_tgemm(
    const float* __restrict__ A, const float* __restrict__ B,
    const float* __restrict__ bias, float* __restrict__ C,
    int M, int K, int N, const float* __restrict__ thrp)
{
    const int PA = 24;   // A smem pitch (bf16 elems): conflict-free frag loads
    const int PB = 20;   // B smem pitch
    __shared__ __align__(16) __nv_bfloat16 As_hi[2][128][PA];
    __shared__ __align__(16) __nv_bfloat16 As_lo[2][128][PA];
    __shared__ __align__(16) __nv_bfloat16 Bs_hi[2][128][PB];
    __shared__ __align__(16) __nv_bfloat16 Bs_lo[2][128][PB];

    int tid = threadIdx.x;
    int lane = tid & 31, warp = tid >> 5;
    int wm = warp >> 2;        // 0..1  (64 rows each)
    int wn = warp & 3;         // 0..3  (32 cols each)
    int fr = lane >> 2;        // 0..7
    int fc = lane & 3;         // 0..3
    int m0 = blockIdx.y * 128, n0 = blockIdx.x * 128;

    // A loader mapping: 256 thr cover 128 rows x 16 k; thread -> row tid>>1, 8 k at (tid&1)*8
    int arow = tid >> 1;
    int aks  = (tid & 1) * 8;
    // B loader: 16 k-rows x 128 n; slots s = tid, tid+256; krow=s>>5, n=(s&31)*4 (4 elems)

    float acc[4][4][4];
#pragma unroll
    for (int mi = 0; mi < 4; mi++)
#pragma unroll
        for (int ni = 0; ni < 4; ni++)
#pragma unroll
            for (int q = 0; q < 4; q++) acc[mi][ni][q] = 0.f;

    float fa[8], fb[8];
    int nch = CDIV(K, 16);

    // ---- global load of chunk kc into registers ----
#define LDG_CHUNK(kc) do { \
    int k0_ = (kc) * 16; \
    long long ar_ = m0 + arow; \
    const float* pA_ = A + (size_t)ar_ * K + k0_ + aks; \
    bool rok_ = ar_ < M; \
    _Pragma("unroll") \
    for (int j = 0; j < 8; j++) { \
        int k_ = k0_ + aks + j; \
        fa[j] = (rok_ && k_ < K) ? pA_[j] : 0.f; \
    } \
    _Pragma("unroll") \
    for (int s2 = 0; s2 < 2; s2++) { \
        int s_ = tid + s2 * 256; \
        int kr_ = s_ >> 5, nn_ = (s_ & 31) * 4; \
        int kg_ = k0_ + kr_; \
        const float* pB_ = B + (size_t)kg_ * N + n0 + nn_; \
        _Pragma("unroll") \
        for (int i = 0; i < 4; i++) { \
            int n_ = n0 + nn_ + i; \
            fb[s2 * 4 + i] = (kg_ < K && n_ < N) ? pB_[i] : 0.f; \
        } \
    } \
} while (0)

    // ---- convert + store registers into smem buffer b ----
#define STS_CHUNK(b) do { \
    _Pragma("unroll") \
    for (int i = 0; i < 4; i++) { \
        float v0_ = fa[2 * i], v1_ = fa[2 * i + 1]; \
        __nv_bfloat16 h0_ = __float2bfloat16(v0_); \
        __nv_bfloat16 h1_ = __float2bfloat16(v1_); \
        __nv_bfloat16 l0_ = __float2bfloat16(v0_ - __bfloat162float(h0_)); \
        __nv_bfloat16 l1_ = __float2bfloat16(v1_ - __bfloat162float(h1_)); \
        __nv_bfloat162 hh_; hh_.x = h0_; hh_.y = h1_; \
        __nv_bfloat162 ll_; ll_.x = l0_; ll_.y = l1_; \
        *(__nv_bfloat162*)&As_hi[b][arow][aks + 2 * i] = hh_; \
        *(__nv_bfloat162*)&As_lo[b][arow][aks + 2 * i] = ll_; \
    } \
    _Pragma("unroll") \
    for (int s2 = 0; s2 < 2; s2++) { \
        int s_ = tid + s2 * 256; \
        int kr_ = s_ >> 5, nn_ = (s_ & 31) * 4; \
        _Pragma("unroll") \
        for (int i = 0; i < 4; i++) { \
            float v_ = fb[s2 * 4 + i]; \
            __nv_bfloat16 h_ = __float2bfloat16(v_); \
            __nv_bfloat16 l_ = __float2bfloat16(v_ - __bfloat162float(h_)); \
            Bs_hi[b][nn_ + i][kr_] = h_; \
            Bs_lo[b][nn_ + i][kr_] = l_; \
        } \
    } \
} while (0)

    LDG_CHUNK(0);
    STS_CHUNK(0);
    __syncthreads();

    int buf = 0;
    for (int ch = 0; ch < nch; ch++) {
        bool more = (ch + 1) < nch;
        if (more) LDG_CHUNK(ch + 1);

        // fragment loads (mma m16n8k16 layouts, derived):
        //  A(row-major 16x16): a0=[fr][2fc,2fc+1] a1=[fr+8][..] a2=[fr][2fc+8..] a3=[fr+8][2fc+8..]
        //  B(16x8, b0 holds B[2fc][fr],B[2fc+1][fr] -> contiguous k in Bs[n][k]) b1: k+8
        uint32_t ah[4][4], al[4][4], bh[4][2], bl[4][2];
#pragma unroll
        for (int mi = 0; mi < 4; mi++) {
            int r = wm * 64 + mi * 16 + fr;
            const __nv_bfloat16* ph = &As_hi[buf][r][fc * 2];
            const __nv_bfloat16* pl = &As_lo[buf][r][fc * 2];
            ah[mi][0] = *(const uint32_t*)(ph);
            ah[mi][1] = *(const uint32_t*)(ph + 8 * PA);
            ah[mi][2] = *(const uint32_t*)(ph + 8);
            ah[mi][3] = *(const uint32_t*)(ph + 8 * PA + 8);
            al[mi][0] = *(const uint32_t*)(pl);
            al[mi][1] = *(const uint32_t*)(pl + 8 * PA);
            al[mi][2] = *(const uint32_t*)(pl + 8);
            al[mi][3] = *(const uint32_t*)(pl + 8 * PA + 8);
        }
#pragma unroll
        for (int ni = 0; ni < 4; ni++) {
            int c = wn * 32 + ni * 8 + fr;
            const __nv_bfloat16* ph = &Bs_hi[buf][c][fc * 2];
            const __nv_bfloat16* pl = &Bs_lo[buf][c][fc * 2];
            bh[ni][0] = *(const uint32_t*)(ph);
            bh[ni][1] = *(const uint32_t*)(ph + 8);
            bl[ni][0] = *(const uint32_t*)(pl);
            bl[ni][1] = *(const uint32_t*)(pl + 8);
        }
#pragma unroll
        for (int mi = 0; mi < 4; mi++)
#pragma unroll
            for (int ni = 0; ni < 4; ni++) {
                MMA_BF16(acc[mi][ni], ah[mi], bh[ni]);
                MMA_BF16(acc[mi][ni], ah[mi], bl[ni]);
                MMA_BF16(acc[mi][ni], al[mi], bh[ni]);
            }

        if (more) STS_CHUNK(buf ^ 1);
        __syncthreads();
        buf ^= 1;
    }

    float thr = (EPI == 2) ? *thrp : 0.f;
#pragma unroll
    for (int mi = 0; mi < 4; mi++) {
#pragma unroll
        for (int ni = 0; ni < 4; ni++) {
            int r0 = m0 + wm * 64 + mi * 16 + fr;
            int c0 = n0 + wn * 32 + ni * 8 + fc * 2;
#pragma unroll
            for (int q = 0; q < 4; q++) {
                int r = r0 + (q >> 1) * 8;
                int c = c0 + (q & 1);
                if (r < M && c < N) {
                    float z = acc[mi][ni][q];
                    if (bias) z += bias[c];
                    if (EPI == 1) z = fmaxf(z, 0.f);
                    if (EPI == 2) z = fmaxf(z - thr, 0.f);
                    C[(size_t)r * N + c] = z;
                }
            }
        }
    }
#undef LDG_CHUNK
#undef STS_CHUNK
}

// ---------------- GCN aggregation: h[i] = elu(sum_{j->i} w*t[j] + dinv_i^2*t[i] + b) ----
template <int F>
__global__ void k_agg(const float* __restrict__ t, const float* __restrict__ bias,
                      float* __restrict__ h)
{
    int node = blockIdx.x;
    int f = threadIdx.x;
    float di = g_dinv[node];
    float acc = di * di * t[(size_t)node * F + f];
    int beg = g_rowptr[node], end = g_rowptr[node + 1];
    __shared__ int scol[128];
    __shared__ float sw[128];
    for (int base = beg; base < end; base += 128) {
        int nchunk = min(128, end - base);
        __syncthreads();
        if (f < nchunk) { scol[f] = g_col[base + f]; sw[f] = g_w[base + f]; }
        __syncthreads();
        for (int j = 0; j < nchunk; j++)
            acc += sw[j] * t[(size_t)scol[j] * F + f];
    }
    float z = acc + bias[f];
    h[(size_t)node * F + f] = (z > 0.f) ? z : expm1f(z);
}

// ---------------- pair gather + L2 normalize ----------------
__global__ void k_pairs(const float* __restrict__ h, const void* i1, const void* i2) {
    int b = blockIdx.x;
    int k = threadIdx.x;  // 128
    int a1 = ld_idx(i1, b), a2 = ld_idx(i2, b);
    float v1 = h[(size_t)a1 * 128 + k];
    float v2 = h[(size_t)a2 * 128 + k];
    float s = v1 * v1 + v2 * v2;
    __shared__ float red[4];
#pragma unroll
    for (int o = 16; o; o >>= 1) s += __shfl_down_sync(0xffffffffu, s, o);
    if ((k & 31) == 0) red[k >> 5] = s;
    __syncthreads();
    float tot = red[0] + red[1] + red[2] + red[3];
    float nrm = fmaxf(sqrtf(tot), 1e-12f);
    float inv = 1.f / nrm;
    g_xc[(size_t)b * 256 + k] = v1 * inv;
    g_xc[(size_t)b * 256 + 128 + k] = v2 * inv;
}

// ---------------- final 64->2 linear ----------------
__global__ void k_out(const float* __restrict__ W, const float* __restrict__ bias,
                      float* __restrict__ out) {
    int b = blockIdx.x;
    int lane = threadIdx.x;  // 32
    float a0 = 0.f, a1 = 0.f;
    for (int k = lane; k < 64; k += 32) {
        float v = g_p3[(size_t)b * 64 + k];
        a0 += v * W[k * 2 + 0];
        a1 += v * W[k * 2 + 1];
    }
#pragma unroll
    for (int o = 16; o; o >>= 1) {
        a0 += __shfl_down_sync(0xffffffffu, a0, o);
        a1 += __shfl_down_sync(0xffffffffu, a1, o);
    }
    if (lane == 0) {
        out[b * 2 + 0] = a0 + bias[0];
        out[b * 2 + 1] = a1 + bias[1];
    }
}

// ---------------- launch ----------------
extern "C" void kernel_launch(void* const* d_in, const int* in_sizes, int n_in,
                              void* d_out, int out_size)
{
    const float* cid   = (const float*)d_in[0];
    const void*  edges = d_in[1];
    const void*  i1    = d_in[2];
    const void*  i2    = d_in[3];
    const float* thr   = (const float*)d_in[4];
    const float* bbW2  = (const float*)d_in[5];
    const float* bbb2  = (const float*)d_in[6];
    const float* bbW3  = (const float*)d_in[7];
    const float* bbb3  = (const float*)d_in[8];
    const float* gW[5] = {(const float*)d_in[9],  (const float*)d_in[11],
                          (const float*)d_in[13], (const float*)d_in[15],
                          (const float*)d_in[17]};
    const float* gb[5] = {(const float*)d_in[10], (const float*)d_in[12],
                          (const float*)d_in[14], (const float*)d_in[16],
                          (const float*)d_in[18]};
    const float* fc1W = (const float*)d_in[19];
    const float* fc1b = (const float*)d_in[20];
    const float* fc2W = (const float*)d_in[21];
    const float* fc2b = (const float*)d_in[22];
    const float* fc3W = (const float*)d_in[23];
    const float* fc3b = (const float*)d_in[24];
    const float* oW   = (const float*)d_in[25];
    const float* ob   = (const float*)d_in[26];
    float* out = (float*)d_out;

    float *x881, *h, *t, *xc, *p1, *p3;
    cudaGetSymbolAddress((void**)&x881, g_x881);
    cudaGetSymbolAddress((void**)&h,    g_h);
    cudaGetSymbolAddress((void**)&t,    g_t);
    cudaGetSymbolAddress((void**)&xc,   g_xc);
    cudaGetSymbolAddress((void**)&p1,   g_p1);
    cudaGetSymbolAddress((void**)&p3,   g_p3);

    // preproc (big GEMM placed 4th — the slot ncu sampled last round)
    k_init<<<CDIV(N_NODES, 256), 256>>>((const unsigned int*)edges);
    k_count<<<CDIV(N_EDGES, 256), 256>>>(edges);
    k_dinv<<<CDIV(N_NODES, 256), 256>>>();
    k_tgemm<2><<<dim3(CDIV(881, 128), CDIV(N_NODES, 128)), 256>>>(
        cid, bbW2, bbb2, x881, N_NODES, 881, 881, thr);
    k_scan<<<1, 1024>>>();
    k_fill<<<CDIV(N_EDGES, 256), 256>>>(edges);

    k_tgemm<1><<<dim3(CDIV(256, 128), CDIV(N_NODES, 128)), 256>>>(
        x881, bbW3, bbb3, h, N_NODES, 881, 256, nullptr);

    // 5 GCN layers
    const int fin[5]  = {256, 256, 256, 256, 128};
    const int fout[5] = {256, 256, 256, 128, 128};
    for (int l = 0; l < 5; l++) {
        k_tgemm<0><<<dim3(CDIV(fout[l], 128), CDIV(N_NODES, 128)), 256>>>(
            h, gW[l], nullptr, t, N_NODES, fin[l], fout[l], nullptr);
        if (fout[l] == 256)
            k_agg<256><<<N_NODES, 256>>>(t, gb[l], h);
        else
            k_agg<128><<<N_NODES, 128>>>(t, gb[l], h);
    }

    // pair readout
    k_pairs<<<B_PAIRS, 128>>>(h, i1, i2);
    k_tgemm<1><<<dim3(CDIV(1024, 128), CDIV(B_PAIRS, 128)), 256>>>(
        xc, fc1W, fc1b, p1, B_PAIRS, 256, 1024, nullptr);
    k_tgemm<1><<<dim3(CDIV(256, 128), CDIV(B_PAIRS, 128)), 256>>>(
        p1, fc2W, fc2b, xc, B_PAIRS, 1024, 256, nullptr);
    k_tgemm<1><<<dim3(CDIV(64, 128), CDIV(B_PAIRS, 128)), 256>>>(
        xc, fc3W, fc3b, p3, B_PAIRS, 256, 64, nullptr);
    k_out<<<B_PAIRS, 32>>>(oW, ob, out);
}

// round 10
// speedup vs baseline: 2.3217x; 1.5107x over previous
#include <cuda_runtime.h>
#include <cuda_bf16.h>
#include <math.h>
#include <stdint.h>

#define N_NODES 30000
#define N_EDGES 480000
#define B_PAIRS 4096
#define CDIV(a,b) (((a)+(b)-1)/(b))

// ---------------- scratch (static device memory; no allocations) ----------------
__device__ float g_x881[N_NODES * 881];
__device__ float g_h[N_NODES * 256];
__device__ float g_t[N_NODES * 256];
__device__ float g_dinv[N_NODES];
__device__ int   g_cnt[N_NODES];
__device__ int   g_fill[N_NODES];
__device__ int   g_rowptr[N_NODES + 1];
__device__ int   g_col[N_EDGES];
__device__ float g_w[N_EDGES];
__device__ float g_xc[B_PAIRS * 256];
__device__ float g_p1[B_PAIRS * 1024];
__device__ float g_p3[B_PAIRS * 64];
__device__ int   g_is64;

// ---------------- fused init: zero counters + detect index dtype ----------------
__global__ void k_init(const unsigned int* p) {
    int i = blockIdx.x * blockDim.x + threadIdx.x;
    if (i < N_NODES) { g_cnt[i] = 0; g_fill[i] = 0; }
    if (blockIdx.x == 0) {
        __shared__ int any;
        if (threadIdx.x == 0) any = 0;
        __syncthreads();
        int loc = 0;
        for (int j = threadIdx.x; j < 2048; j += blockDim.x)
            if (p[2 * j + 1] != 0u) loc = 1;
        if (loc) any = 1;
        __syncthreads();
        if (threadIdx.x == 0) g_is64 = (any == 0);
    }
}

__device__ __forceinline__ int ld_idx(const void* p, long long i) {
    if (g_is64) return (int)((const long long*)p)[i];
    return ((const int*)p)[i];
}

// ---------------- graph preprocessing ----------------
__global__ void k_count(const void* edges) {
    int e = blockIdx.x * blockDim.x + threadIdx.x;
    if (e >= N_EDGES) return;
    int d = ld_idx(edges, (long long)N_EDGES + e);
    atomicAdd(&g_cnt[d], 1);
}

__global__ void k_dinv() {
    int i = blockIdx.x * blockDim.x + threadIdx.x;
    if (i < N_NODES) g_dinv[i] = rsqrtf((float)(g_cnt[i] + 1));
}

__global__ void k_scan() {
    __shared__ int s[1024];
    __shared__ int carry;
    int t = threadIdx.x;
    if (t == 0) { carry = 0; g_rowptr[0] = 0; }
    __syncthreads();
    for (int base = 0; base < N_NODES; base += 1024) {
        int i = base + t;
        int v = (i < N_NODES) ? g_cnt[i] : 0;
        s[t] = v;
        __syncthreads();
        for (int off = 1; off < 1024; off <<= 1) {
            int add = (t >= off) ? s[t - off] : 0;
            __syncthreads();
            s[t] += add;
            __syncthreads();
        }
        if (i < N_NODES) g_rowptr[i + 1] = carry + s[t];
        __syncthreads();
        if (t == 0) carry += s[1023];
        __syncthreads();
    }
}

__global__ void k_fill(const void* edges) {
    int e = blockIdx.x * blockDim.x + threadIdx.x;
    if (e >= N_EDGES) return;
    int s = ld_idx(edges, e);
    int d = ld_idx(edges, (long long)N_EDGES + e);
    int pos = g_rowptr[d] + atomicAdd(&g_fill[d], 1);
    g_col[pos] = s;
    g_w[pos] = g_dinv[s] * g_dinv[d];
}

// =====================================================================
// bf16-split tensor GEMM with ldmatrix:  C = epi(A[M,K] @ B[K,N] + bias)
// a = ahi + alo (bf16 each);  C ≈ Ahi Bhi + Ahi Blo + Alo Bhi
// Block 128x128, 8 warps (2m x 4n), warp tile 64x32, BK=16, double buffered.
// A smem: [128][24] row-major k (LDSM non-trans); B smem: [16][136] k-major
// (vector STS, LDSM .trans).  EPI 0: none  1: relu  2: relu+softthr
// =====================================================================
#define MMA_BF16(d, a0, a1, a2, a3, b0, b1) \
    asm volatile("mma.sync.aligned.m16n8k16.row.col.f32.bf16.bf16.f32 " \
                 "{%0,%1,%2,%3},{%4,%5,%6,%7},{%8,%9},{%0,%1,%2,%3};" \
                 : "+f"(d[0]), "+f"(d[1]), "+f"(d[2]), "+f"(d[3]) \
                 : "r"(a0), "r"(a1), "r"(a2), "r"(a3), "r"(b0), "r"(b1))

__device__ __forceinline__ void ldsm_x4(uint32_t& r0, uint32_t& r1, uint32_t& r2,
                                        uint32_t& r3, uint32_t addr) {
    asm volatile("ldmatrix.sync.aligned.m8n8.x4.shared.b16 {%0,%1,%2,%3},[%4];"
                 : "=r"(r0), "=r"(r1), "=r"(r2), "=r"(r3) : "r"(addr));
}
__device__ __forceinline__ void ldsm_x4_t(uint32_t& r0, uint32_t& r1, uint32_t& r2,
                                          uint32_t& r3, uint32_t addr) {
    asm volatile("ldmatrix.sync.aligned.m8n8.x4.trans.shared.b16 {%0,%1,%2,%3},[%4];"
                 : "=r"(r0), "=r"(r1), "=r"(r2), "=r"(r3) : "r"(addr));
}

template <int EPI>
__global__ __launch_bounds__(256, 2) void k_tgemm(
    const float* __restrict__ A, const float* __restrict__ B,
    const float* __restrict__ bias, float* __restrict__ C,
    int M, int K, int N, const float* __restrict__ thrp)
{
    const int PA = 24;    // A pitch (bf16): 48B rows, 16B-aligned, LDSM conflict-free
    const int PBN = 136;  // B pitch (bf16): 272B rows, LDSM-trans conflict-free
    __shared__ __align__(16) __nv_bfloat16 As_hi[2][128][PA];
    __shared__ __align__(16) __nv_bfloat16 As_lo[2][128][PA];
    __shared__ __align__(16) __nv_bfloat16 Bs_hi[2][16][PBN];
    __shared__ __align__(16) __nv_bfloat16 Bs_lo[2][16][PBN];

    int tid = threadIdx.x;
    int lane = tid & 31, warp = tid >> 5;
    int wm = warp >> 2;        // 0..1  (64 rows)
    int wn = warp & 3;         // 0..3  (32 cols)
    int fr = lane >> 2;        // 0..7
    int fc = lane & 3;         // 0..3
    int m0 = blockIdx.y * 128, n0 = blockIdx.x * 128;

    // A loader: thread -> row tid>>1, 8 consecutive k at (tid&1)*8
    int arow = tid >> 1;
    int aks  = (tid & 1) * 8;

    // ldmatrix lane addressing
    int a_r = (lane & 15);           // row within 16-row tile
    int a_c = (lane >> 4) * 8;       // k column 0 or 8
    int b_k = (lane & 7) + ((lane >> 3) & 1) * 8;   // k row 0..15
    int b_c = (lane >> 4) * 8;       // n column offset 0 or 8

    uint32_t sAhi = (uint32_t)__cvta_generic_to_shared(&As_hi[0][0][0]);
    uint32_t sAlo = (uint32_t)__cvta_generic_to_shared(&As_lo[0][0][0]);
    uint32_t sBhi = (uint32_t)__cvta_generic_to_shared(&Bs_hi[0][0][0]);
    uint32_t sBlo = (uint32_t)__cvta_generic_to_shared(&Bs_lo[0][0][0]);

    float acc[4][4][4];
#pragma unroll
    for (int mi = 0; mi < 4; mi++)
#pragma unroll
        for (int ni = 0; ni < 4; ni++)
#pragma unroll
            for (int q = 0; q < 4; q++) acc[mi][ni][q] = 0.f;

    float fa[8], fb[8];
    int nch = CDIV(K, 16);

#define LDG_CHUNK(kc) do { \
    int k0_ = (kc) * 16; \
    long long ar_ = m0 + arow; \
    const float* pA_ = A + (size_t)ar_ * K + k0_ + aks; \
    bool rok_ = ar_ < M; \
    _Pragma("unroll") \
    for (int j = 0; j < 8; j++) { \
        int k_ = k0_ + aks + j; \
        fa[j] = (rok_ && k_ < K) ? pA_[j] : 0.f; \
    } \
    _Pragma("unroll") \
    for (int s2 = 0; s2 < 2; s2++) { \
        int s_ = tid + s2 * 256; \
        int kr_ = s_ >> 5, nn_ = (s_ & 31) * 4; \
        int kg_ = k0_ + kr_; \
        const float* pB_ = B + (size_t)kg_ * N + n0 + nn_; \
        _Pragma("unroll") \
        for (int i = 0; i < 4; i++) { \
            int n_ = n0 + nn_ + i; \
            fb[s2 * 4 + i] = (kg_ < K && n_ < N) ? pB_[i] : 0.f; \
        } \
    } \
} while (0)

#define STS_CHUNK(b) do { \
    _Pragma("unroll") \
    for (int i = 0; i < 4; i++) { \
        float v0_ = fa[2 * i], v1_ = fa[2 * i + 1]; \
        __nv_bfloat16 h0_ = __float2bfloat16(v0_); \
        __nv_bfloat16 h1_ = __float2bfloat16(v1_); \
        __nv_bfloat16 l0_ = __float2bfloat16(v0_ - __bfloat162float(h0_)); \
        __nv_bfloat16 l1_ = __float2bfloat16(v1_ - __bfloat162float(h1_)); \
        __nv_bfloat162 hh_; hh_.x = h0_; hh_.y = h1_; \
        __nv_bfloat162 ll_; ll_.x = l0_; ll_.y = l1_; \
        *(__nv_bfloat162*)&As_hi[b][arow][aks + 2 * i] = hh_; \
        *(__nv_bfloat162*)&As_lo[b][arow][aks + 2 * i] = ll_; \
    } \
    _Pragma("unroll") \
    for (int s2 = 0; s2 < 2; s2++) { \
        int s_ = tid + s2 * 256; \
        int kr_ = s_ >> 5, nn_ = (s_ & 31) * 4; \
        union { __nv_bfloat162 h2[2]; uint2 u; } ph_, pl_; \
        _Pragma("unroll") \
        for (int i = 0; i < 2; i++) { \
            float w0_ = fb[s2 * 4 + 2 * i], w1_ = fb[s2 * 4 + 2 * i + 1]; \
            __nv_bfloat16 h0_ = __float2bfloat16(w0_); \
            __nv_bfloat16 h1_ = __float2bfloat16(w1_); \
            __nv_bfloat16 l0_ = __float2bfloat16(w0_ - __bfloat162float(h0_)); \
            __nv_bfloat16 l1_ = __float2bfloat16(w1_ - __bfloat162float(h1_)); \
            ph_.h2[i].x = h0_; ph_.h2[i].y = h1_; \
            pl_.h2[i].x = l0_; pl_.h2[i].y = l1_; \
        } \
        *(uint2*)&Bs_hi[b][kr_][nn_] = ph_.u; \
        *(uint2*)&Bs_lo[b][kr_][nn_] = pl_.u; \
    } \
} while (0)

    LDG_CHUNK(0);
    STS_CHUNK(0);
    __syncthreads();

    int buf = 0;
    for (int ch = 0; ch < nch; ch++) {
        bool more = (ch + 1) < nch;
        if (more) LDG_CHUNK(ch + 1);

        // ---- A fragments via ldmatrix (non-trans) ----
        uint32_t ah[4][4], al[4][4];
#pragma unroll
        for (int mi = 0; mi < 4; mi++) {
            uint32_t off = (uint32_t)(((buf * 128 + wm * 64 + mi * 16 + a_r) * PA + a_c) * 2);
            ldsm_x4(ah[mi][0], ah[mi][1], ah[mi][2], ah[mi][3], sAhi + off);
            ldsm_x4(al[mi][0], al[mi][1], al[mi][2], al[mi][3], sAlo + off);
        }
        // ---- B fragments via ldmatrix.trans; pair p covers ni=2p, 2p+1 ----
#pragma unroll
        for (int p = 0; p < 2; p++) {
            int c0 = wn * 32 + p * 16;
            uint32_t off = (uint32_t)(((buf * 16 + b_k) * PBN + c0 + b_c) * 2);
            uint32_t bh0, bh1, bh2, bh3, bl0, bl1, bl2, bl3;
            ldsm_x4_t(bh0, bh1, bh2, bh3, sBhi + off);
            ldsm_x4_t(bl0, bl1, bl2, bl3, sBlo + off);
#pragma unroll
            for (int mi = 0; mi < 4; mi++) {
                MMA_BF16(acc[mi][2 * p], ah[mi][0], ah[mi][1], ah[mi][2], ah[mi][3], bh0, bh1);
                MMA_BF16(acc[mi][2 * p], ah[mi][0], ah[mi][1], ah[mi][2], ah[mi][3], bl0, bl1);
                MMA_BF16(acc[mi][2 * p], al[mi][0], al[mi][1], al[mi][2], al[mi][3], bh0, bh1);
                MMA_BF16(acc[mi][2 * p + 1], ah[mi][0], ah[mi][1], ah[mi][2], ah[mi][3], bh2, bh3);
                MMA_BF16(acc[mi][2 * p + 1], ah[mi][0], ah[mi][1], ah[mi][2], ah[mi][3], bl2, bl3);
                MMA_BF16(acc[mi][2 * p + 1], al[mi][0], al[mi][1], al[mi][2], al[mi][3], bh2, bh3);
            }
        }

        if (more) STS_CHUNK(buf ^ 1);
        __syncthreads();
        buf ^= 1;
    }

    float thr = (EPI == 2) ? *thrp : 0.f;
#pragma unroll
    for (int mi = 0; mi < 4; mi++) {
#pragma unroll
        for (int ni = 0; ni < 4; ni++) {
            int r0 = m0 + wm * 64 + mi * 16 + fr;
            int c0 = n0 + wn * 32 + ni * 8 + fc * 2;
#pragma unroll
            for (int q = 0; q < 4; q++) {
                int r = r0 + (q >> 1) * 8;
                int c = c0 + (q & 1);
                if (r < M && c < N) {
                    float z = acc[mi][ni][q];
                    if (bias) z += bias[c];
                    if (EPI == 1) z = fmaxf(z, 0.f);
                    if (EPI == 2) z = fmaxf(z - thr, 0.f);
                    C[(size_t)r * N + c] = z;
                }
            }
        }
    }
#undef LDG_CHUNK
#undef STS_CHUNK
}

// ---------------- GCN aggregation: h[i] = elu(sum_{j->i} w*t[j] + dinv_i^2*t[i] + b) ----
template <int F>
__global__ void k_agg(const float* __restrict__ t, const float* __restrict__ bias,
                      float* __restrict__ h)
{
    int node = blockIdx.x;
    int f = threadIdx.x;
    float di = g_dinv[node];
    float acc = di * di * t[(size_t)node * F + f];
    int beg = g_rowptr[node], end = g_rowptr[node + 1];
    __shared__ int scol[128];
    __shared__ float sw[128];
    for (int base = beg; base < end; base += 128) {
        int nchunk = min(128, end - base);
        __syncthreads();
        if (f < nchunk) { scol[f] = g_col[base + f]; sw[f] = g_w[base + f]; }
        __syncthreads();
        for (int j = 0; j < nchunk; j++)
            acc += sw[j] * t[(size_t)scol[j] * F + f];
    }
    float z = acc + bias[f];
    h[(size_t)node * F + f] = (z > 0.f) ? z : expm1f(z);
}

// ---------------- pair gather + L2 normalize ----------------
__global__ void k_pairs(const float* __restrict__ h, const void* i1, const void* i2) {
    int b = blockIdx.x;
    int k = threadIdx.x;  // 128
    int a1 = ld_idx(i1, b), a2 = ld_idx(i2, b);
    float v1 = h[(size_t)a1 * 128 + k];
    float v2 = h[(size_t)a2 * 128 + k];
    float s = v1 * v1 + v2 * v2;
    __shared__ float red[4];
#pragma unroll
    for (int o = 16; o; o >>= 1) s += __shfl_down_sync(0xffffffffu, s, o);
    if ((k & 31) == 0) red[k >> 5] = s;
    __syncthreads();
    float tot = red[0] + red[1] + red[2] + red[3];
    float nrm = fmaxf(sqrtf(tot), 1e-12f);
    float inv = 1.f / nrm;
    g_xc[(size_t)b * 256 + k] = v1 * inv;
    g_xc[(size_t)b * 256 + 128 + k] = v2 * inv;
}

// ---------------- final 64->2 linear ----------------
__global__ void k_out(const float* __restrict__ W, const float* __restrict__ bias,
                      float* __restrict__ out) {
    int b = blockIdx.x;
    int lane = threadIdx.x;  // 32
    float a0 = 0.f, a1 = 0.f;
    for (int k = lane; k < 64; k += 32) {
        float v = g_p3[(size_t)b * 64 + k];
        a0 += v * W[k * 2 + 0];
        a1 += v * W[k * 2 + 1];
    }
#pragma unroll
    for (int o = 16; o; o >>= 1) {
        a0 += __shfl_down_sync(0xffffffffu, a0, o);
        a1 += __shfl_down_sync(0xffffffffu, a1, o);
    }
    if (lane == 0) {
        out[b * 2 + 0] = a0 + bias[0];
        out[b * 2 + 1] = a1 + bias[1];
    }
}

// ---------------- launch ----------------
extern "C" void kernel_launch(void* const* d_in, const int* in_sizes, int n_in,
                              void* d_out, int out_size)
{
    const float* cid   = (const float*)d_in[0];
    const void*  edges = d_in[1];
    const void*  i1    = d_in[2];
    const void*  i2    = d_in[3];
    const float* thr   = (const float*)d_in[4];
    const float* bbW2  = (const float*)d_in[5];
    const float* bbb2  = (const float*)d_in[6];
    const float* bbW3  = (const float*)d_in[7];
    const float* bbb3  = (const float*)d_in[8];
    const float* gW[5] = {(const float*)d_in[9],  (const float*)d_in[11],
                          (const float*)d_in[13], (const float*)d_in[15],
                          (const float*)d_in[17]};
    const float* gb[5] = {(const float*)d_in[10], (const float*)d_in[12],
                          (const float*)d_in[14], (const float*)d_in[16],
                          (const float*)d_in[18]};
    const float* fc1W = (const float*)d_in[19];
    const float* fc1b = (const float*)d_in[20];
    const float* fc2W = (const float*)d_in[21];
    const float* fc2b = (const float*)d_in[22];
    const float* fc3W = (const float*)d_in[23];
    const float* fc3b = (const float*)d_in[24];
    const float* oW   = (const float*)d_in[25];
    const float* ob   = (const float*)d_in[26];
    float* out = (float*)d_out;

    float *x881, *h, *t, *xc, *p1, *p3;
    cudaGetSymbolAddress((void**)&x881, g_x881);
    cudaGetSymbolAddress((void**)&h,    g_h);
    cudaGetSymbolAddress((void**)&t,    g_t);
    cudaGetSymbolAddress((void**)&xc,   g_xc);
    cudaGetSymbolAddress((void**)&p1,   g_p1);
    cudaGetSymbolAddress((void**)&p3,   g_p3);

    // preproc (big GEMM stays 4th — ncu -s 5 -c 1 samples it)
    k_init<<<CDIV(N_NODES, 256), 256>>>((const unsigned int*)edges);
    k_count<<<CDIV(N_EDGES, 256), 256>>>(edges);
    k_dinv<<<CDIV(N_NODES, 256), 256>>>();
    k_tgemm<2><<<dim3(CDIV(881, 128), CDIV(N_NODES, 128)), 256>>>(
        cid, bbW2, bbb2, x881, N_NODES, 881, 881, thr);
    k_scan<<<1, 1024>>>();
    k_fill<<<CDIV(N_EDGES, 256), 256>>>(edges);

    k_tgemm<1><<<dim3(CDIV(256, 128), CDIV(N_NODES, 128)), 256>>>(
        x881, bbW3, bbb3, h, N_NODES, 881, 256, nullptr);

    // 5 GCN layers
    const int fin[5]  = {256, 256, 256, 256, 128};
    const int fout[5] = {256, 256, 256, 128, 128};
    for (int l = 0; l < 5; l++) {
        k_tgemm<0><<<dim3(CDIV(fout[l], 128), CDIV(N_NODES, 128)), 256>>>(
            h, gW[l], nullptr, t, N_NODES, fin[l], fout[l], nullptr);
        if (fout[l] == 256)
            k_agg<256><<<N_NODES, 256>>>(t, gb[l], h);
        else
            k_agg<128><<<N_NODES, 128>>>(t, gb[l], h);
    }

    // pair readout
    k_pairs<<<B_PAIRS, 128>>>(h, i1, i2);
    k_tgemm<1><<<dim3(CDIV(1024, 128), CDIV(B_PAIRS, 128)), 256>>>(
        xc, fc1W, fc1b, p1, B_PAIRS, 256, 1024, nullptr);
    k_tgemm<1><<<dim3(CDIV(256, 128), CDIV(B_PAIRS, 128)), 256>>>(
        p1, fc2W, fc2b, xc, B_PAIRS, 1024, 256, nullptr);
    k_tgemm<1><<<dim3(CDIV(64, 128), CDIV(B_PAIRS, 128)), 256>>>(
        xc, fc3W, fc3b, p3, B_PAIRS, 256, 64, nullptr);
    k_out<<<B_PAIRS, 32>>>(oW, ob, out);
}